// round 6
// baseline (speedup 1.0000x reference)
#include <cuda_runtime.h>
#include <cuda_bf16.h>
#include <math.h>

// ---------------------------------------------------------------------------
// SimplifiedSSMLayer: B=8, S=4096, D_MODEL=1024, D_STATE=16
// Round 6: GEMM retile to 128x256 (512 thr, 16 warps) to halve x DRAM traffic;
// combine_ln vectorized with float4.
// ---------------------------------------------------------------------------

#define BATCH   8
#define SEQ     4096
#define DM      1024
#define NS      16
#define T_TOK   (BATCH*SEQ)          // 32768

__device__ float g_Bx[T_TOK * NS];               // 2 MB
__device__ float g_states[T_TOK * NS];           // 2 MB
__device__ float g_gate[(size_t)T_TOK * DM];     // 128 MB

// ---------------------------------------------------------------------------
// K1: Bx = x @ B_w^T + B_b   (round-3 version: 256 blocks, ~50us measured)
// ---------------------------------------------------------------------------
__global__ void __launch_bounds__(256) bx_kernel(const float* __restrict__ x,
                                                 const float* __restrict__ B_w,
                                                 const float* __restrict__ B_b)
{
    extern __shared__ float Bw_s[];  // [16][1024]
    const int tid = threadIdx.x;
    for (int i = tid; i < (NS * DM) / 4; i += 256)
        reinterpret_cast<float4*>(Bw_s)[i] = reinterpret_cast<const float4*>(B_w)[i];
    __syncthreads();

    const int w = tid >> 5, lane = tid & 31;
    const int tbase = blockIdx.x * 128 + w * 16;

    for (int g = 0; g < 4; ++g) {
        const int t0 = tbase + g * 4;
        float acc[4][NS];
#pragma unroll
        for (int tt = 0; tt < 4; ++tt)
#pragma unroll
            for (int n = 0; n < NS; ++n) acc[tt][n] = 0.f;

#pragma unroll 2
        for (int c = 0; c < 8; ++c) {
            const int k0 = c * 128 + lane * 4;
            float4 xv[4];
#pragma unroll
            for (int tt = 0; tt < 4; ++tt)
                xv[tt] = *reinterpret_cast<const float4*>(&x[(size_t)(t0 + tt) * DM + k0]);
#pragma unroll
            for (int n = 0; n < NS; ++n) {
                const float4 bw = *reinterpret_cast<const float4*>(&Bw_s[n * DM + k0]);
#pragma unroll
                for (int tt = 0; tt < 4; ++tt) {
                    acc[tt][n] = fmaf(xv[tt].x, bw.x, acc[tt][n]);
                    acc[tt][n] = fmaf(xv[tt].y, bw.y, acc[tt][n]);
                    acc[tt][n] = fmaf(xv[tt].z, bw.z, acc[tt][n]);
                    acc[tt][n] = fmaf(xv[tt].w, bw.w, acc[tt][n]);
                }
            }
        }
#pragma unroll
        for (int tt = 0; tt < 4; ++tt) {
            float outv = 0.f;
#pragma unroll
            for (int n = 0; n < NS; ++n) {
                float v = acc[tt][n];
                v += __shfl_xor_sync(0xffffffffu, v, 16);
                v += __shfl_xor_sync(0xffffffffu, v, 8);
                v += __shfl_xor_sync(0xffffffffu, v, 4);
                v += __shfl_xor_sync(0xffffffffu, v, 2);
                v += __shfl_xor_sync(0xffffffffu, v, 1);
                if (lane == n) outv = v;
            }
            if (lane < NS)
                g_Bx[(size_t)(t0 + tt) * NS + lane] = outv + B_b[lane];
        }
    }
}

// ---------------------------------------------------------------------------
// K2: scan (blocks 0..63) + tf32 mma.sync gate GEMM (blocks 64..1087)
// GEMM: 128x256 CTA tile, 512 threads, 16 warps (4M x 4N of 32x64),
//       BK=32, 3-stage cp.async, ldmatrix fragments.
// ---------------------------------------------------------------------------
#define GTM 128
#define GTN 256
#define GBK 32
#define GSTAGES (DM / GBK)                // 32
#define N_MTILES (T_TOK / GTM)            // 256
#define N_NTILES (DM / GTN)               // 4
#define GEMM_BLOCKS (N_MTILES * N_NTILES) // 1024
#define SCAN_BLOCKS 64

#define ROWSTRIDE 36                      // floats; ldsm conflict-free
#define A_FLOATS (GTM * ROWSTRIDE)        // 4608
#define B_FLOATS (GTN * ROWSTRIDE)        // 9216
#define STAGE_FLOATS (A_FLOATS + B_FLOATS)// 13824
#define STAGE_BYTES (STAGE_FLOATS * 4)    // 55296
#define NPIPE 3
#define GEMM_SMEM (NPIPE * STAGE_BYTES)   // 165888

#define SCAN_CHUNK 64
#define SCAN_WARM  64

__device__ __forceinline__ unsigned smem_u32(const void* p) {
    unsigned a;
    asm("{ .reg .u64 t; cvta.to.shared.u64 t, %1; cvt.u32.u64 %0, t; }"
        : "=r"(a) : "l"(p));
    return a;
}
__device__ __forceinline__ void cp16(unsigned dst, const void* src) {
    asm volatile("cp.async.cg.shared.global [%0], [%1], 16;"
                 :: "r"(dst), "l"(src) : "memory");
}
__device__ __forceinline__ void ldsm4(unsigned& r0, unsigned& r1,
                                      unsigned& r2, unsigned& r3, unsigned a) {
    asm volatile("ldmatrix.sync.aligned.m8n8.x4.shared.b16 {%0,%1,%2,%3}, [%4];"
                 : "=r"(r0), "=r"(r1), "=r"(r2), "=r"(r3) : "r"(a));
}

__global__ void __launch_bounds__(512, 1) gemm_scan_kernel(
    const float* __restrict__ x, const float* __restrict__ A,
    const float* __restrict__ gate_w, const float* __restrict__ gate_b)
{
    extern __shared__ float smemf[];

    if (blockIdx.x < SCAN_BLOCKS) {
        // ------------------ parallel scan (contraction warm-up) ------------
        if (threadIdx.x >= 128) return;
        const int sb = blockIdx.x;
        const int warp = threadIdx.x >> 5, lane = threadIdx.x & 31;
        const int chunk = sb * 8 + warp * 2 + (lane >> 4); // 0..511
        const int i = lane & 15;
        const int batch = chunk >> 6;
        const int cib = chunk & 63;
        const int t0 = cib * SCAN_CHUNK;
        const int ts = (cib == 0) ? 0 : (t0 - SCAN_WARM);

        float a[NS];
#pragma unroll
        for (int j = 0; j < NS; ++j) a[j] = __ldg(&A[i * NS + j]);

        const float* bxp = g_Bx + (size_t)batch * SEQ * NS;
        float* stp = g_states + (size_t)batch * SEQ * NS;
        float s = 0.f;
        for (int t = ts; t < t0 + SCAN_CHUNK; ++t) {
            const float bx = bxp[t * NS + i];
            float sv[NS];
#pragma unroll
            for (int j = 0; j < NS; ++j) sv[j] = __shfl_sync(0xffffffffu, s, j, 16);
            float p0 = fmaf(a[0], sv[0], fmaf(a[1], sv[1], fmaf(a[2], sv[2], a[3] * sv[3])));
            float p1 = fmaf(a[4], sv[4], fmaf(a[5], sv[5], fmaf(a[6], sv[6], a[7] * sv[7])));
            float p2 = fmaf(a[8], sv[8], fmaf(a[9], sv[9], fmaf(a[10], sv[10], a[11] * sv[11])));
            float p3 = fmaf(a[12], sv[12], fmaf(a[13], sv[13], fmaf(a[14], sv[14], a[15] * sv[15])));
            s = tanhf(bx + ((p0 + p1) + (p2 + p3)));
            if (t >= t0) stp[t * NS + i] = s;
        }
        return;
    }

    // ------------------------- GEMM path --------------------------------
    const int tile = blockIdx.x - SCAN_BLOCKS;
    const int m0 = (tile >> 2) * GTM;
    const int n0 = (tile & 3) * GTN;

    const int tid = threadIdx.x;
    const int wid = tid >> 5;
    const int lane = tid & 31;
    const int wm = (wid & 3) * 32;      // warp M offset (4 warps x 32 = 128)
    const int wn = (wid >> 2) * 64;     // warp N offset (4 warps x 64 = 256)
    const int lq = lane >> 2;           // 0..7
    const int lr = lane & 3;            // 0..3

    const unsigned sbase = smem_u32(smemf);

    // ldmatrix per-thread source rows
    const int a_row = wm + (lane & 7) + ((lane >> 3) & 1) * 8;   // + mi*16
    const int a_kx  = (lane >> 4) * 4;
    const int b_row = wn + (lane & 7) + ((lane >> 4) & 1) * 8;   // + nip*16
    const int b_kx  = ((lane >> 3) & 1) * 4;

    // --- cp.async stage: A 18KB + B 36KB ---
    auto cp_stage = [&](int s) {
        const int kc = s * GBK;
        const unsigned sA = sbase + (unsigned)(s % NPIPE) * STAGE_BYTES;
        const unsigned sB = sA + A_FLOATS * 4;
#pragma unroll
        for (int q = 0; q < 2; ++q) {
            const int j = tid + 512 * q;     // 0..1023
            const int row = j >> 3;
            const int kg = j & 7;
            cp16(sA + row * (ROWSTRIDE * 4) + kg * 16,
                 &x[(size_t)(m0 + row) * DM + kc + kg * 4]);
        }
#pragma unroll
        for (int q = 0; q < 4; ++q) {
            const int j = tid + 512 * q;     // 0..2047
            const int row = j >> 3;
            const int kg = j & 7;
            cp16(sB + row * (ROWSTRIDE * 4) + kg * 16,
                 &gate_w[(size_t)(n0 + row) * DM + kc + kg * 4]);
        }
        asm volatile("cp.async.commit_group;" ::: "memory");
    };

    float c[2][8][4];
#pragma unroll
    for (int mi = 0; mi < 2; ++mi)
#pragma unroll
        for (int ni = 0; ni < 8; ++ni)
#pragma unroll
            for (int r = 0; r < 4; ++r) c[mi][ni][r] = 0.f;

    cp_stage(0);
    cp_stage(1);

    for (int s = 0; s < GSTAGES; ++s) {
        asm volatile("cp.async.wait_group 1;" ::: "memory");
        __syncthreads();

        const unsigned stg = sbase + (unsigned)(s % NPIPE) * STAGE_BYTES;
        const unsigned aAddr0 = stg + (unsigned)((a_row)*ROWSTRIDE + a_kx) * 4u;
        const unsigned bAddr0 = stg + (unsigned)(A_FLOATS + (b_row)*ROWSTRIDE + b_kx) * 4u;

#pragma unroll
        for (int ks = 0; ks < 4; ++ks) {
            const int k0 = ks * 8;
            unsigned af[2][4];
#pragma unroll
            for (int mi = 0; mi < 2; ++mi)
                ldsm4(af[mi][0], af[mi][1], af[mi][2], af[mi][3],
                      aAddr0 + (unsigned)(mi * 16 * ROWSTRIDE + k0) * 4u);
            unsigned bf[8][2];
#pragma unroll
            for (int nip = 0; nip < 4; ++nip)
                ldsm4(bf[nip * 2][0], bf[nip * 2][1],
                      bf[nip * 2 + 1][0], bf[nip * 2 + 1][1],
                      bAddr0 + (unsigned)(nip * 16 * ROWSTRIDE + k0) * 4u);
#pragma unroll
            for (int mi = 0; mi < 2; ++mi)
#pragma unroll
                for (int ni = 0; ni < 8; ++ni) {
                    asm volatile(
                        "mma.sync.aligned.m16n8k8.row.col.f32.tf32.tf32.f32 "
                        "{%0,%1,%2,%3}, {%4,%5,%6,%7}, {%8,%9}, {%0,%1,%2,%3};"
                        : "+f"(c[mi][ni][0]), "+f"(c[mi][ni][1]),
                          "+f"(c[mi][ni][2]), "+f"(c[mi][ni][3])
                        : "r"(af[mi][0]), "r"(af[mi][1]),
                          "r"(af[mi][2]), "r"(af[mi][3]),
                          "r"(bf[ni][0]), "r"(bf[ni][1]));
                }
        }
        if (s + 2 < GSTAGES) cp_stage(s + 2);
    }

    // --- epilogue: silu(acc + gate_b) -> g_gate ---
#pragma unroll
    for (int ni = 0; ni < 8; ++ni) {
        const int col = n0 + wn + ni * 8 + lr * 2;
        const float2 gb = *reinterpret_cast<const float2*>(&gate_b[col]);
#pragma unroll
        for (int mi = 0; mi < 2; ++mi) {
            const int row0 = m0 + wm + mi * 16 + lq;
#pragma unroll
            for (int h = 0; h < 2; ++h) {
                const int row = row0 + h * 8;
                float z0 = c[mi][ni][h * 2 + 0] + gb.x;
                float z1 = c[mi][ni][h * 2 + 1] + gb.y;
                float2 o;
                o.x = z0 / (1.0f + __expf(-z0));
                o.y = z1 / (1.0f + __expf(-z1));
                *reinterpret_cast<float2*>(&g_gate[(size_t)row * DM + col]) = o;
            }
        }
    }
}

// ---------------------------------------------------------------------------
// K3: fused  so = states@C_w^T + C_b + D*x ; o = g*so+(1-g)*x ; r = o+x ; LN
// float4-vectorized: thread handles 4 contiguous elements.
// ---------------------------------------------------------------------------
__global__ void __launch_bounds__(256) combine_ln_kernel(
    const float* __restrict__ x, const float* __restrict__ C_w,
    const float* __restrict__ C_b, const float* __restrict__ Dv,
    const float* __restrict__ ln_g, const float* __restrict__ ln_b,
    float* __restrict__ out)
{
    __shared__ float st_s[8][NS];
    __shared__ float r_s[8][DM];
    __shared__ float wsum[8][8], wsq[8][8];
    __shared__ float mu_s[8], rs_s[8];

    const int tid = threadIdx.x;
    const int tok0 = blockIdx.x * 8;
    const int e0 = tid * 4;

    if (tid < 128)
        st_s[tid >> 4][tid & 15] =
            g_states[(size_t)(tok0 + (tid >> 4)) * NS + (tid & 15)];

    float cw[4][NS];
#pragma unroll
    for (int j = 0; j < 4; ++j)
#pragma unroll
        for (int n4 = 0; n4 < 4; ++n4) {
            const float4 v = *reinterpret_cast<const float4*>(&C_w[(e0 + j) * NS + n4 * 4]);
            cw[j][n4 * 4 + 0] = v.x;
            cw[j][n4 * 4 + 1] = v.y;
            cw[j][n4 * 4 + 2] = v.z;
            cw[j][n4 * 4 + 3] = v.w;
        }
    const float4 cb4 = *reinterpret_cast<const float4*>(&C_b[e0]);
    const float4 dv4 = *reinterpret_cast<const float4*>(&Dv[e0]);
    const float4 lg4 = *reinterpret_cast<const float4*>(&ln_g[e0]);
    const float4 lb4 = *reinterpret_cast<const float4*>(&ln_b[e0]);
    __syncthreads();

    const int warp = tid >> 5, lane = tid & 31;
#pragma unroll 2
    for (int r = 0; r < 8; ++r) {
        const size_t t = (size_t)(tok0 + r);
        const float4 xv = *reinterpret_cast<const float4*>(&x[t * DM + e0]);
        const float4 gv = *reinterpret_cast<const float4*>(&g_gate[t * DM + e0]);

        float so[4] = {cb4.x, cb4.y, cb4.z, cb4.w};
#pragma unroll
        for (int n = 0; n < NS; ++n) {
            const float st = st_s[r][n];
            so[0] = fmaf(st, cw[0][n], so[0]);
            so[1] = fmaf(st, cw[1][n], so[1]);
            so[2] = fmaf(st, cw[2][n], so[2]);
            so[3] = fmaf(st, cw[3][n], so[3]);
        }
        so[0] = fmaf(dv4.x, xv.x, so[0]);
        so[1] = fmaf(dv4.y, xv.y, so[1]);
        so[2] = fmaf(dv4.z, xv.z, so[2]);
        so[3] = fmaf(dv4.w, xv.w, so[3]);

        float4 rr;
        rr.x = fmaf(gv.x, so[0] - xv.x, xv.x) + xv.x;
        rr.y = fmaf(gv.y, so[1] - xv.y, xv.y) + xv.y;
        rr.z = fmaf(gv.z, so[2] - xv.z, xv.z) + xv.z;
        rr.w = fmaf(gv.w, so[3] - xv.w, xv.w) + xv.w;
        *reinterpret_cast<float4*>(&r_s[r][e0]) = rr;

        float ps = (rr.x + rr.y) + (rr.z + rr.w);
        float pq = fmaf(rr.x, rr.x, rr.y * rr.y) + fmaf(rr.z, rr.z, rr.w * rr.w);
#pragma unroll
        for (int off = 16; off; off >>= 1) {
            ps += __shfl_xor_sync(0xffffffffu, ps, off);
            pq += __shfl_xor_sync(0xffffffffu, pq, off);
        }
        if (lane == 0) { wsum[r][warp] = ps; wsq[r][warp] = pq; }
    }
    __syncthreads();

    if (tid < 8) {
        float s = 0.f, s2 = 0.f;
#pragma unroll
        for (int w = 0; w < 8; ++w) { s += wsum[tid][w]; s2 += wsq[tid][w]; }
        const float mu = s * (1.0f / DM);
        float var = s2 * (1.0f / DM) - mu * mu;
        var = fmaxf(var, 0.f);
        mu_s[tid] = mu;
        rs_s[tid] = rsqrtf(var + 1e-5f);
    }
    __syncthreads();

#pragma unroll 2
    for (int r = 0; r < 8; ++r) {
        const size_t t = (size_t)(tok0 + r);
        const float mu = mu_s[r], rs = rs_s[r];
        const float4 rr = *reinterpret_cast<const float4*>(&r_s[r][e0]);
        float4 o;
        o.x = (rr.x - mu) * rs * lg4.x + lb4.x;
        o.y = (rr.y - mu) * rs * lg4.y + lb4.y;
        o.z = (rr.z - mu) * rs * lg4.z + lb4.z;
        o.w = (rr.w - mu) * rs * lg4.w + lb4.w;
        *reinterpret_cast<float4*>(&out[t * DM + e0]) = o;
    }
}

// ---------------------------------------------------------------------------
extern "C" void kernel_launch(void* const* d_in, const int* in_sizes, int n_in,
                              void* d_out, int out_size)
{
    const float* x      = (const float*)d_in[0];
    const float* A      = (const float*)d_in[1];
    const float* B_w    = (const float*)d_in[2];
    const float* B_b    = (const float*)d_in[3];
    const float* C_w    = (const float*)d_in[4];
    const float* C_b    = (const float*)d_in[5];
    const float* Dv     = (const float*)d_in[6];
    const float* gate_w = (const float*)d_in[7];
    const float* gate_b = (const float*)d_in[8];
    const float* ln_g   = (const float*)d_in[9];
    const float* ln_b   = (const float*)d_in[10];
    float* out = (float*)d_out;

    cudaFuncSetAttribute(bx_kernel, cudaFuncAttributeMaxDynamicSharedMemorySize,
                         NS * DM * (int)sizeof(float));
    cudaFuncSetAttribute(gemm_scan_kernel, cudaFuncAttributeMaxDynamicSharedMemorySize,
                         GEMM_SMEM);

    bx_kernel<<<256, 256, NS * DM * sizeof(float)>>>(x, B_w, B_b);
    gemm_scan_kernel<<<SCAN_BLOCKS + GEMM_BLOCKS, 512, GEMM_SMEM>>>(x, A, gate_w, gate_b);
    combine_ln_kernel<<<T_TOK / 8, 256>>>(x, C_w, C_b, Dv, ln_g, ln_b, out);
}

// round 8
// speedup vs baseline: 1.0374x; 1.0374x over previous
#include <cuda_runtime.h>
#include <cuda_bf16.h>
#include <math.h>

// ---------------------------------------------------------------------------
// SimplifiedSSMLayer: B=8, S=4096, D_MODEL=1024, D_STATE=16
// Round 8: overlap via kernel-boundary sync (no spin-waits):
//   K2a = bx + GEMM tiles [0,1024)      (bx independent of GEMM)
//   K2b = scan + GEMM tiles [1024,2048) (scan sees completed g_Bx)
//   K3  = float4 combine + LayerNorm
// GEMM config = round-5 best (128x128, BK=32, 3-stage, ldmatrix, 2 CTA/SM).
// ---------------------------------------------------------------------------

#define BATCH   8
#define SEQ     4096
#define DM      1024
#define NS      16
#define T_TOK   (BATCH*SEQ)          // 32768

__device__ float g_Bx[T_TOK * NS];               // 2 MB
__device__ float g_states[T_TOK * NS];           // 2 MB
__device__ float g_gate[(size_t)T_TOK * DM];     // 128 MB

#define BX_GRID 256
#define SCAN_BLOCKS 64

#define GTM 128
#define GTN 128
#define GBK 32
#define GSTAGES (DM / GBK)                // 32
#define GEMM_BLOCKS 2048                  // total GEMM tiles
#define GEMM_HALF 1024

#define ROWSTRIDE 36                      // floats; ldsm conflict-free
#define A_FLOATS (GTM * ROWSTRIDE)        // 4608
#define STAGE_FLOATS (2 * A_FLOATS)       // 9216
#define STAGE_BYTES (STAGE_FLOATS * 4)    // 36864
#define NPIPE 3
#define GEMM_SMEM (NPIPE * STAGE_BYTES)   // 110592 -> 2 CTAs/SM

#define SCAN_CHUNK 64
#define SCAN_WARM  64

__device__ __forceinline__ unsigned smem_u32(const void* p) {
    unsigned a;
    asm("{ .reg .u64 t; cvta.to.shared.u64 t, %1; cvt.u32.u64 %0, t; }"
        : "=r"(a) : "l"(p));
    return a;
}
__device__ __forceinline__ void cp16(unsigned dst, const void* src) {
    asm volatile("cp.async.cg.shared.global [%0], [%1], 16;"
                 :: "r"(dst), "l"(src) : "memory");
}
__device__ __forceinline__ void ldsm4(unsigned& r0, unsigned& r1,
                                      unsigned& r2, unsigned& r3, unsigned a) {
    asm volatile("ldmatrix.sync.aligned.m8n8.x4.shared.b16 {%0,%1,%2,%3}, [%4];"
                 : "=r"(r0), "=r"(r1), "=r"(r2), "=r"(r3) : "r"(a));
}

// ---------------------------------------------------------------------------
// Shared GEMM tile body (round-5 config)
// ---------------------------------------------------------------------------
__device__ __forceinline__ void gemm_tile_body(
    int tile, const float* __restrict__ x,
    const float* __restrict__ gate_w, const float* __restrict__ gate_b,
    float* smemf)
{
    const int m0 = (tile >> 3) * GTM;
    const int n0 = (tile & 7) * GTN;

    const int tid = threadIdx.x;
    const int wid = tid >> 5;
    const int lane = tid & 31;
    const int wm = (wid & 3) * 32;
    const int wn = (wid >> 2) * 64;
    const int lq = lane >> 2;
    const int lr = lane & 3;

    const unsigned sbase = smem_u32(smemf);

    const int a_row = wm + (lane & 7) + ((lane >> 3) & 1) * 8;   // + mi*16
    const int a_kx  = (lane >> 4) * 4;
    const int b_row = wn + (lane & 7) + ((lane >> 4) & 1) * 8;   // + nip*16
    const int b_kx  = ((lane >> 3) & 1) * 4;

    auto cp_stage = [&](int s) {
        const int kc = s * GBK;
        const unsigned sA = sbase + (unsigned)(s % NPIPE) * STAGE_BYTES;
        const unsigned sB = sA + A_FLOATS * 4;
#pragma unroll
        for (int q = 0; q < 4; ++q) {
            const int j = tid + 256 * q;
            const int row = j >> 3;
            const int kg = j & 7;
            cp16(sA + row * (ROWSTRIDE * 4) + kg * 16,
                 &x[(size_t)(m0 + row) * DM + kc + kg * 4]);
            cp16(sB + row * (ROWSTRIDE * 4) + kg * 16,
                 &gate_w[(size_t)(n0 + row) * DM + kc + kg * 4]);
        }
        asm volatile("cp.async.commit_group;" ::: "memory");
    };

    float c[2][8][4];
#pragma unroll
    for (int mi = 0; mi < 2; ++mi)
#pragma unroll
        for (int ni = 0; ni < 8; ++ni)
#pragma unroll
            for (int r = 0; r < 4; ++r) c[mi][ni][r] = 0.f;

    cp_stage(0);
    cp_stage(1);

    for (int s = 0; s < GSTAGES; ++s) {
        asm volatile("cp.async.wait_group 1;" ::: "memory");
        __syncthreads();

        const unsigned stg = sbase + (unsigned)(s % NPIPE) * STAGE_BYTES;
        const unsigned aAddr0 = stg + (unsigned)((a_row)*ROWSTRIDE + a_kx) * 4u;
        const unsigned bAddr0 = stg + (unsigned)(A_FLOATS + (b_row)*ROWSTRIDE + b_kx) * 4u;

#pragma unroll
        for (int ks = 0; ks < 4; ++ks) {
            const int k0 = ks * 8;
            unsigned af[2][4];
#pragma unroll
            for (int mi = 0; mi < 2; ++mi)
                ldsm4(af[mi][0], af[mi][1], af[mi][2], af[mi][3],
                      aAddr0 + (unsigned)(mi * 16 * ROWSTRIDE + k0) * 4u);
            unsigned bf[8][2];
#pragma unroll
            for (int nip = 0; nip < 4; ++nip)
                ldsm4(bf[nip * 2][0], bf[nip * 2][1],
                      bf[nip * 2 + 1][0], bf[nip * 2 + 1][1],
                      bAddr0 + (unsigned)(nip * 16 * ROWSTRIDE + k0) * 4u);
#pragma unroll
            for (int mi = 0; mi < 2; ++mi)
#pragma unroll
                for (int ni = 0; ni < 8; ++ni) {
                    asm volatile(
                        "mma.sync.aligned.m16n8k8.row.col.f32.tf32.tf32.f32 "
                        "{%0,%1,%2,%3}, {%4,%5,%6,%7}, {%8,%9}, {%0,%1,%2,%3};"
                        : "+f"(c[mi][ni][0]), "+f"(c[mi][ni][1]),
                          "+f"(c[mi][ni][2]), "+f"(c[mi][ni][3])
                        : "r"(af[mi][0]), "r"(af[mi][1]),
                          "r"(af[mi][2]), "r"(af[mi][3]),
                          "r"(bf[ni][0]), "r"(bf[ni][1]));
                }
        }
        if (s + 2 < GSTAGES) cp_stage(s + 2);
    }

#pragma unroll
    for (int ni = 0; ni < 8; ++ni) {
        const int col = n0 + wn + ni * 8 + lr * 2;
        const float2 gb = *reinterpret_cast<const float2*>(&gate_b[col]);
#pragma unroll
        for (int mi = 0; mi < 2; ++mi) {
            const int row0 = m0 + wm + mi * 16 + lq;
#pragma unroll
            for (int h = 0; h < 2; ++h) {
                const int row = row0 + h * 8;
                float z0 = c[mi][ni][h * 2 + 0] + gb.x;
                float z1 = c[mi][ni][h * 2 + 1] + gb.y;
                float2 o;
                o.x = z0 / (1.0f + __expf(-z0));
                o.y = z1 / (1.0f + __expf(-z1));
                *reinterpret_cast<float2*>(&g_gate[(size_t)row * DM + col]) = o;
            }
        }
    }
}

// ---------------------------------------------------------------------------
// K2a: bx (blocks 0..255) + GEMM tiles [0,1024)
// ---------------------------------------------------------------------------
__global__ void __launch_bounds__(256, 2) k2a_kernel(
    const float* __restrict__ x,
    const float* __restrict__ B_w, const float* __restrict__ B_b,
    const float* __restrict__ gate_w, const float* __restrict__ gate_b)
{
    extern __shared__ float smemf[];
    const int tid = threadIdx.x;

    if (blockIdx.x < BX_GRID) {
        // bx: Bx = x @ B_w^T + B_b
        float* Bw_s = smemf;
        for (int i = tid; i < (NS * DM) / 4; i += 256)
            reinterpret_cast<float4*>(Bw_s)[i] = reinterpret_cast<const float4*>(B_w)[i];
        __syncthreads();

        const int w = tid >> 5, lane = tid & 31;
        const int tbase = blockIdx.x * 128 + w * 16;

        for (int g = 0; g < 4; ++g) {
            const int t0 = tbase + g * 4;
            float acc[4][NS];
#pragma unroll
            for (int tt = 0; tt < 4; ++tt)
#pragma unroll
                for (int n = 0; n < NS; ++n) acc[tt][n] = 0.f;

#pragma unroll 2
            for (int c = 0; c < 8; ++c) {
                const int k0 = c * 128 + lane * 4;
                float4 xv[4];
#pragma unroll
                for (int tt = 0; tt < 4; ++tt)
                    xv[tt] = *reinterpret_cast<const float4*>(&x[(size_t)(t0 + tt) * DM + k0]);
#pragma unroll
                for (int n = 0; n < NS; ++n) {
                    const float4 bw = *reinterpret_cast<const float4*>(&Bw_s[n * DM + k0]);
#pragma unroll
                    for (int tt = 0; tt < 4; ++tt) {
                        acc[tt][n] = fmaf(xv[tt].x, bw.x, acc[tt][n]);
                        acc[tt][n] = fmaf(xv[tt].y, bw.y, acc[tt][n]);
                        acc[tt][n] = fmaf(xv[tt].z, bw.z, acc[tt][n]);
                        acc[tt][n] = fmaf(xv[tt].w, bw.w, acc[tt][n]);
                    }
                }
            }
#pragma unroll
            for (int tt = 0; tt < 4; ++tt) {
                float outv = 0.f;
#pragma unroll
                for (int n = 0; n < NS; ++n) {
                    float v = acc[tt][n];
                    v += __shfl_xor_sync(0xffffffffu, v, 16);
                    v += __shfl_xor_sync(0xffffffffu, v, 8);
                    v += __shfl_xor_sync(0xffffffffu, v, 4);
                    v += __shfl_xor_sync(0xffffffffu, v, 2);
                    v += __shfl_xor_sync(0xffffffffu, v, 1);
                    if (lane == n) outv = v;
                }
                if (lane < NS)
                    g_Bx[(size_t)(t0 + tt) * NS + lane] = outv + B_b[lane];
            }
        }
        return;
    }

    gemm_tile_body(blockIdx.x - BX_GRID, x, gate_w, gate_b, smemf);
}

// ---------------------------------------------------------------------------
// K2b: scan (blocks 0..63) + GEMM tiles [1024,2048)
// ---------------------------------------------------------------------------
__global__ void __launch_bounds__(256, 2) k2b_kernel(
    const float* __restrict__ x, const float* __restrict__ A,
    const float* __restrict__ gate_w, const float* __restrict__ gate_b)
{
    extern __shared__ float smemf[];
    const int tid = threadIdx.x;

    if (blockIdx.x < SCAN_BLOCKS) {
        if (tid >= 128) return;
        const int sb = blockIdx.x;
        const int warp = tid >> 5, lane = tid & 31;
        const int chunk = sb * 8 + warp * 2 + (lane >> 4); // 0..511
        const int i = lane & 15;
        const int batch = chunk >> 6;
        const int cib = chunk & 63;
        const int t0 = cib * SCAN_CHUNK;
        const int ts = (cib == 0) ? 0 : (t0 - SCAN_WARM);

        float a[NS];
#pragma unroll
        for (int j = 0; j < NS; ++j) a[j] = __ldg(&A[i * NS + j]);

        const float* bxp = g_Bx + (size_t)batch * SEQ * NS;
        float* stp = g_states + (size_t)batch * SEQ * NS;
        float s = 0.f;
        for (int t = ts; t < t0 + SCAN_CHUNK; ++t) {
            const float bx = bxp[t * NS + i];
            float sv[NS];
#pragma unroll
            for (int j = 0; j < NS; ++j) sv[j] = __shfl_sync(0xffffffffu, s, j, 16);
            float p0 = fmaf(a[0], sv[0], fmaf(a[1], sv[1], fmaf(a[2], sv[2], a[3] * sv[3])));
            float p1 = fmaf(a[4], sv[4], fmaf(a[5], sv[5], fmaf(a[6], sv[6], a[7] * sv[7])));
            float p2 = fmaf(a[8], sv[8], fmaf(a[9], sv[9], fmaf(a[10], sv[10], a[11] * sv[11])));
            float p3 = fmaf(a[12], sv[12], fmaf(a[13], sv[13], fmaf(a[14], sv[14], a[15] * sv[15])));
            s = tanhf(bx + ((p0 + p1) + (p2 + p3)));
            if (t >= t0) stp[t * NS + i] = s;
        }
        return;
    }

    gemm_tile_body(GEMM_HALF + blockIdx.x - SCAN_BLOCKS, x, gate_w, gate_b, smemf);
}

// ---------------------------------------------------------------------------
// K3: fused  so = states@C_w^T + C_b + D*x ; o = g*so+(1-g)*x ; r = o+x ; LN
// float4-vectorized (round-6 version).
// ---------------------------------------------------------------------------
__global__ void __launch_bounds__(256) combine_ln_kernel(
    const float* __restrict__ x, const float* __restrict__ C_w,
    const float* __restrict__ C_b, const float* __restrict__ Dv,
    const float* __restrict__ ln_g, const float* __restrict__ ln_b,
    float* __restrict__ out)
{
    __shared__ float st_s[8][NS];
    __shared__ float r_s[8][DM];
    __shared__ float wsum[8][8], wsq[8][8];
    __shared__ float mu_s[8], rs_s[8];

    const int tid = threadIdx.x;
    const int tok0 = blockIdx.x * 8;
    const int e0 = tid * 4;

    if (tid < 128)
        st_s[tid >> 4][tid & 15] =
            g_states[(size_t)(tok0 + (tid >> 4)) * NS + (tid & 15)];

    float cw[4][NS];
#pragma unroll
    for (int j = 0; j < 4; ++j)
#pragma unroll
        for (int n4 = 0; n4 < 4; ++n4) {
            const float4 v = *reinterpret_cast<const float4*>(&C_w[(e0 + j) * NS + n4 * 4]);
            cw[j][n4 * 4 + 0] = v.x;
            cw[j][n4 * 4 + 1] = v.y;
            cw[j][n4 * 4 + 2] = v.z;
            cw[j][n4 * 4 + 3] = v.w;
        }
    const float4 cb4 = *reinterpret_cast<const float4*>(&C_b[e0]);
    const float4 dv4 = *reinterpret_cast<const float4*>(&Dv[e0]);
    const float4 lg4 = *reinterpret_cast<const float4*>(&ln_g[e0]);
    const float4 lb4 = *reinterpret_cast<const float4*>(&ln_b[e0]);
    __syncthreads();

    const int warp = tid >> 5, lane = tid & 31;
#pragma unroll 2
    for (int r = 0; r < 8; ++r) {
        const size_t t = (size_t)(tok0 + r);
        const float4 xv = *reinterpret_cast<const float4*>(&x[t * DM + e0]);
        const float4 gv = *reinterpret_cast<const float4*>(&g_gate[t * DM + e0]);

        float so[4] = {cb4.x, cb4.y, cb4.z, cb4.w};
#pragma unroll
        for (int n = 0; n < NS; ++n) {
            const float st = st_s[r][n];
            so[0] = fmaf(st, cw[0][n], so[0]);
            so[1] = fmaf(st, cw[1][n], so[1]);
            so[2] = fmaf(st, cw[2][n], so[2]);
            so[3] = fmaf(st, cw[3][n], so[3]);
        }
        so[0] = fmaf(dv4.x, xv.x, so[0]);
        so[1] = fmaf(dv4.y, xv.y, so[1]);
        so[2] = fmaf(dv4.z, xv.z, so[2]);
        so[3] = fmaf(dv4.w, xv.w, so[3]);

        float4 rr;
        rr.x = fmaf(gv.x, so[0] - xv.x, xv.x) + xv.x;
        rr.y = fmaf(gv.y, so[1] - xv.y, xv.y) + xv.y;
        rr.z = fmaf(gv.z, so[2] - xv.z, xv.z) + xv.z;
        rr.w = fmaf(gv.w, so[3] - xv.w, xv.w) + xv.w;
        *reinterpret_cast<float4*>(&r_s[r][e0]) = rr;

        float ps = (rr.x + rr.y) + (rr.z + rr.w);
        float pq = fmaf(rr.x, rr.x, rr.y * rr.y) + fmaf(rr.z, rr.z, rr.w * rr.w);
#pragma unroll
        for (int off = 16; off; off >>= 1) {
            ps += __shfl_xor_sync(0xffffffffu, ps, off);
            pq += __shfl_xor_sync(0xffffffffu, pq, off);
        }
        if (lane == 0) { wsum[r][warp] = ps; wsq[r][warp] = pq; }
    }
    __syncthreads();

    if (tid < 8) {
        float s = 0.f, s2 = 0.f;
#pragma unroll
        for (int w = 0; w < 8; ++w) { s += wsum[tid][w]; s2 += wsq[tid][w]; }
        const float mu = s * (1.0f / DM);
        float var = s2 * (1.0f / DM) - mu * mu;
        var = fmaxf(var, 0.f);
        mu_s[tid] = mu;
        rs_s[tid] = rsqrtf(var + 1e-5f);
    }
    __syncthreads();

#pragma unroll 2
    for (int r = 0; r < 8; ++r) {
        const size_t t = (size_t)(tok0 + r);
        const float mu = mu_s[r], rs = rs_s[r];
        const float4 rr = *reinterpret_cast<const float4*>(&r_s[r][e0]);
        float4 o;
        o.x = (rr.x - mu) * rs * lg4.x + lb4.x;
        o.y = (rr.y - mu) * rs * lg4.y + lb4.y;
        o.z = (rr.z - mu) * rs * lg4.z + lb4.z;
        o.w = (rr.w - mu) * rs * lg4.w + lb4.w;
        *reinterpret_cast<float4*>(&out[t * DM + e0]) = o;
    }
}

// ---------------------------------------------------------------------------
extern "C" void kernel_launch(void* const* d_in, const int* in_sizes, int n_in,
                              void* d_out, int out_size)
{
    const float* x      = (const float*)d_in[0];
    const float* A      = (const float*)d_in[1];
    const float* B_w    = (const float*)d_in[2];
    const float* B_b    = (const float*)d_in[3];
    const float* C_w    = (const float*)d_in[4];
    const float* C_b    = (const float*)d_in[5];
    const float* Dv     = (const float*)d_in[6];
    const float* gate_w = (const float*)d_in[7];
    const float* gate_b = (const float*)d_in[8];
    const float* ln_g   = (const float*)d_in[9];
    const float* ln_b   = (const float*)d_in[10];
    float* out = (float*)d_out;

    cudaFuncSetAttribute(k2a_kernel, cudaFuncAttributeMaxDynamicSharedMemorySize,
                         GEMM_SMEM);
    cudaFuncSetAttribute(k2b_kernel, cudaFuncAttributeMaxDynamicSharedMemorySize,
                         GEMM_SMEM);

    k2a_kernel<<<BX_GRID + GEMM_HALF, 256, GEMM_SMEM>>>(x, B_w, B_b, gate_w, gate_b);
    k2b_kernel<<<SCAN_BLOCKS + GEMM_HALF, 256, GEMM_SMEM>>>(x, A, gate_w, gate_b);
    combine_ln_kernel<<<T_TOK / 8, 256>>>(x, C_w, C_b, Dv, ln_g, ln_b, out);
}